// round 7
// baseline (speedup 1.0000x reference)
#include <cuda_runtime.h>
#include <cstdint>

#define GN 10000   // nodes
#define GE 64000   // edges
#define GG 64      // graphs
#define HH 64      // hidden
#define XD 128     // input feat
#define EAD 32     // edge attr dim
#define KTOT 4224  // 4096 (S outer) + 64 (sh @ B2) + 64 (h @ root)
#define KSPLIT 6
#define KSEG (KTOT / KSPLIT)      // 704
#define BK 32
#define NCHUNK_KS (KSEG / BK)     // 22
#define EB 16      // edge batch in k_S
#define ADS 66     // As2 row stride in float2 (528B, 16B-aligned)

// ---------------- scratch (static device memory; no allocs allowed) ----------
__device__ float g_hx[GN * HH];                    // node features (in-place per layer)
__device__ float g_hidden[GE * HH];                // edge MLP hidden (relu(ea@w1+b1))
__device__ float g_S[(size_t)GN * KTOT];           // per-node bilinear accumulators + sh + h
__device__ float g_Bcat[KTOT * HH];                // [w2 as 4096x64 ; B2 ; root], row-major [k][o]
__device__ float g_part[KSPLIT][GN * HH];          // K-split partial sums
__device__ int   g_cnt[GN];
__device__ int   g_off[GN + 1];
__device__ int   g_cur[GN];
__device__ int   g_sorted[GE];
__device__ float g_hg[GG * HH];
__device__ int   g_e64;                            // edge_index is int64?
__device__ int   g_b64;                            // batch is int64?

__device__ __forceinline__ long long ld_idx(const void* p, long long i, int is64) {
    return is64 ? ((const long long*)p)[i] : (long long)((const int*)p)[i];
}
__device__ __forceinline__ float lrelu(float v) { return v >= 0.f ? v : 0.01f * v; }

// ---- packed f32x2 helpers (Blackwell FFMA2; base sm_100 PTX) -----------------
__device__ __forceinline__ void unpack2(uint64_t v, float& x, float& y) {
    asm("mov.b64 {%0, %1}, %2;" : "=f"(x), "=f"(y) : "l"(v));
}
__device__ __forceinline__ void ffma2(uint64_t& acc, uint64_t a, uint64_t b) {
    asm("fma.rn.f32x2 %0, %1, %2, %0;" : "+l"(acc) : "l"(a), "l"(b));
}

// ---------------- dtype detection (parallel, one warp) -----------------------
__global__ void k_detect(const void* eidx, const void* batch) {
    int t = threadIdx.x;  // 32 threads
    const long long* p = (const long long*)eidx;
    bool ok = true;
#pragma unroll
    for (int j = 0; j < 4; j++) {
        long long v = p[t + j * 32];
        ok &= (v >= 0 && v < GN);
    }
    unsigned e_ok = __all_sync(0xFFFFFFFFu, ok);
    const long long* b = (const long long*)batch;
    bool okb = true;
#pragma unroll
    for (int j = 0; j < 2; j++) {
        long long v = b[GN / 2 - 64 + t + j * 32];
        okb &= (v >= 0 && v < GG);
    }
    unsigned b_ok = __all_sync(0xFFFFFFFFu, okb);
    if (t == 0) { g_e64 = e_ok ? 1 : 0; g_b64 = b_ok ? 1 : 0; }
}

__global__ void k_zero() {
    int i = blockIdx.x * 256 + threadIdx.x;
    if (i < GN) { g_cnt[i] = 0; g_cur[i] = 0; }
    if (i < GG * HH) g_hg[i] = 0.f;
}

// ---------------- node encoder: hx = lrelu(x @ nfc_w + nfc_b) ----------------
__global__ __launch_bounds__(256) void k_nodefc(const float* __restrict__ x,
                                                const float* __restrict__ w,
                                                const float* __restrict__ b) {
    __shared__ float xs[4][XD];
    int n0 = blockIdx.x * 4;
    int t = threadIdx.x;
#pragma unroll
    for (int q = 0; q < 2; q++) {
        int idx = t + q * 256;
        xs[idx >> 7][idx & 127] = x[(size_t)(n0 + (idx >> 7)) * XD + (idx & 127)];
    }
    __syncthreads();
    int ln = t >> 6, o = t & 63;
    float acc = b[o];
#pragma unroll
    for (int k = 0; k < XD; k++) acc = fmaf(xs[ln][k], w[k * HH + o], acc);
    g_hx[(size_t)(n0 + ln) * HH + o] = lrelu(acc);
}

// ---------------- edge MLP hidden: relu(ea @ w1 + b1) ------------------------
__global__ __launch_bounds__(256) void k_hidden(const float* __restrict__ ea,
                                                const float* __restrict__ w1,
                                                const float* __restrict__ b1) {
    __shared__ float eas[4][EAD];
    int e0 = blockIdx.x * 4;
    int t = threadIdx.x;
    if (t < 128) eas[t >> 5][t & 31] = ea[(size_t)(e0 + (t >> 5)) * EAD + (t & 31)];
    __syncthreads();
    int le = t >> 6, o = t & 63;
    float acc = b1[o];
#pragma unroll
    for (int k = 0; k < EAD; k++) acc = fmaf(eas[le][k], w1[k * HH + o], acc);
    g_hidden[(size_t)(e0 + le) * HH + o] = fmaxf(acc, 0.f);
}

// ---------------- CSR build (counting sort by dst; bucket order = atomic,
// ulp-level nondeterminism only, same as float atomics in k_pool) -------------
__global__ void k_hist(const void* eidx) {
    int e = blockIdx.x * 256 + threadIdx.x;
    if (e >= GE) return;
    int d = (int)ld_idx(eidx, (long long)GE + e, g_e64);
    atomicAdd(&g_cnt[d], 1);
}

__global__ __launch_bounds__(1024) void k_scan() {
    __shared__ int part[1024];
    const int C = 10;
    int t = threadIdx.x;
    int base = t * C;
    int loc[C];
    int s = 0;
#pragma unroll
    for (int j = 0; j < C; j++) {
        int idx = base + j;
        int c = (idx < GN) ? g_cnt[idx] : 0;
        loc[j] = s;
        s += c;
    }
    part[t] = s;
    __syncthreads();
    for (int off = 1; off < 1024; off <<= 1) {
        int v = (t >= off) ? part[t - off] : 0;
        __syncthreads();
        part[t] += v;
        __syncthreads();
    }
    int pre = part[t] - s;  // exclusive prefix
#pragma unroll
    for (int j = 0; j < C; j++) {
        int idx = base + j;
        if (idx <= GN) g_off[idx] = pre + loc[j];
    }
}

__global__ void k_fill(const void* eidx) {
    int e = blockIdx.x * 256 + threadIdx.x;
    if (e >= GE) return;
    int d = (int)ld_idx(eidx, (long long)GE + e, g_e64);
    int pos = g_off[d] + atomicAdd(&g_cur[d], 1);
    g_sorted[pos] = e;
}

// ---------------- B matrix concat: [w2(4096x64); B2(64x64); root(64x64)] -----
__global__ void k_prepB(const float* __restrict__ w2, const float* __restrict__ b2,
                        const float* __restrict__ root) {
    int idx = blockIdx.x * 256 + threadIdx.x;
    if (idx >= KTOT * HH) return;
    int r = idx >> 6, o = idx & 63;
    float v;
    if (r < 4096)       v = w2[idx];                     // (k*64+i)*64+o == k*4096+i*64+o
    else if (r < 4160)  v = b2[(r - 4096) * HH + o];
    else                v = root[(r - 4160) * HH + o];
    g_Bcat[idx] = v;
}

// ---------------- per-node S row: batched outer-product accumulation ---------
__global__ __launch_bounds__(128) void k_S(const void* eidx) {
    int n = blockIdx.x;
    int t = threadIdx.x;
    int k = t >> 1, half = t & 1;
    __shared__ float hid_s[EB][64];
    __shared__ float hsrc_s[EB][68];
    float acc[32];
#pragma unroll
    for (int q = 0; q < 32; q++) acc[q] = 0.f;
    float shacc = 0.f;
    int beg = g_off[n], end = g_off[n + 1];
    int is64 = g_e64;
    for (int b0 = beg; b0 < end; b0 += EB) {
        int nb = min(EB, end - b0);
        __syncthreads();   // previous batch's smem readers done
        for (int idx = t; idx < nb * 16; idx += 128) {
            int le = idx >> 4, q = idx & 15;
            int e = g_sorted[b0 + le];
            long long s = ld_idx(eidx, e, is64);
            *(float4*)&hid_s[le][q * 4]  = *(const float4*)&g_hidden[(size_t)e * HH + q * 4];
            *(float4*)&hsrc_s[le][q * 4] = *(const float4*)&g_hx[(size_t)s * HH + q * 4];
        }
        __syncthreads();
        for (int le = 0; le < nb; le++) {
            float c = hid_s[le][k];
            const float4* hp = (const float4*)&hsrc_s[le][half * 32];
#pragma unroll
            for (int q4 = 0; q4 < 8; q4++) {
                float4 h = hp[q4];
                acc[q4 * 4 + 0] = fmaf(c, h.x, acc[q4 * 4 + 0]);
                acc[q4 * 4 + 1] = fmaf(c, h.y, acc[q4 * 4 + 1]);
                acc[q4 * 4 + 2] = fmaf(c, h.z, acc[q4 * 4 + 2]);
                acc[q4 * 4 + 3] = fmaf(c, h.w, acc[q4 * 4 + 3]);
            }
        }
        if (t < 64) {
            for (int le = 0; le < nb; le++) shacc += hsrc_s[le][t];
        }
    }
    size_t base = (size_t)n * KTOT;
#pragma unroll
    for (int q = 0; q < 32; q += 4) {
        float4 v = make_float4(acc[q], acc[q + 1], acc[q + 2], acc[q + 3]);
        *(float4*)&g_S[base + k * 64 + half * 32 + q] = v;
    }
    if (t < 64) g_S[base + 4096 + t] = shacc;
    else        g_S[base + 4160 + (t - 64)] = g_hx[(size_t)n * HH + (t - 64)];
}

// ---------------- GEMM (K-split): g_part[ks] = S[:, ks-seg] @ Bcat[ks-seg, :]
// A stored DUPLICATED in smem as (a,a) float2 pairs -> inner loop is pure
// 3x LDS.128 + 8x FFMA2 per kk, no operand packing MOVs.
__global__ __launch_bounds__(256) void k_gemm_ks() {
    __shared__ float2 As2[BK][ADS];   // [kk][m] duplicated pairs (row 528B)
    __shared__ float  Bs[BK][64];     // [kk][o]
    int t = threadIdx.x;
    int m0 = blockIdx.x * 64;
    int kbase = blockIdx.y * KSEG;
    int tx = t & 15, ty = t >> 4;

    uint64_t accp[4][2];
#pragma unroll
    for (int i = 0; i < 4; i++) { accp[i][0] = 0ull; accp[i][1] = 0ull; }

    int ar[2], ac4[2], aok[2];
#pragma unroll
    for (int q = 0; q < 2; q++) {
        int idx = t + 256 * q;
        ar[q] = idx >> 3;
        ac4[q] = idx & 7;
        aok[q] = (m0 + ar[q]) < GN;
    }
    float4 ra[2], rb[2];

#pragma unroll
    for (int q = 0; q < 2; q++) {
        ra[q] = aok[q] ? *(const float4*)&g_S[(size_t)(m0 + ar[q]) * KTOT + kbase + ac4[q] * 4]
                       : make_float4(0.f, 0.f, 0.f, 0.f);
        int idx = t + 256 * q;
        rb[q] = *(const float4*)&g_Bcat[(kbase + (idx >> 4)) * 64 + (idx & 15) * 4];
    }

    for (int c = 0; c < NCHUNK_KS; c++) {
        __syncthreads();
#pragma unroll
        for (int q = 0; q < 2; q++) {
            int kb = ac4[q] * 4;
            As2[kb + 0][ar[q]] = make_float2(ra[q].x, ra[q].x);
            As2[kb + 1][ar[q]] = make_float2(ra[q].y, ra[q].y);
            As2[kb + 2][ar[q]] = make_float2(ra[q].z, ra[q].z);
            As2[kb + 3][ar[q]] = make_float2(ra[q].w, ra[q].w);
            int idx = t + 256 * q;
            *(float4*)&Bs[idx >> 4][(idx & 15) * 4] = rb[q];
        }
        __syncthreads();

        if (c + 1 < NCHUNK_KS) {
            int k0 = kbase + (c + 1) * BK;
#pragma unroll
            for (int q = 0; q < 2; q++) {
                ra[q] = aok[q] ? *(const float4*)&g_S[(size_t)(m0 + ar[q]) * KTOT + k0 + ac4[q] * 4]
                               : make_float4(0.f, 0.f, 0.f, 0.f);
                int idx = t + 256 * q;
                rb[q] = *(const float4*)&g_Bcat[(k0 + (idx >> 4)) * 64 + (idx & 15) * 4];
            }
        }

#pragma unroll
        for (int kk = 0; kk < BK; kk++) {
            ulonglong2 A01 = *(const ulonglong2*)&As2[kk][ty * 4];      // (a0,a0),(a1,a1)
            ulonglong2 A23 = *(const ulonglong2*)&As2[kk][ty * 4 + 2];  // (a2,a2),(a3,a3)
            ulonglong2 Bv  = *(const ulonglong2*)&Bs[kk][tx * 4];       // (b0,b1),(b2,b3)
            ffma2(accp[0][0], A01.x, Bv.x); ffma2(accp[0][1], A01.x, Bv.y);
            ffma2(accp[1][0], A01.y, Bv.x); ffma2(accp[1][1], A01.y, Bv.y);
            ffma2(accp[2][0], A23.x, Bv.x); ffma2(accp[2][1], A23.x, Bv.y);
            ffma2(accp[3][0], A23.y, Bv.x); ffma2(accp[3][1], A23.y, Bv.y);
        }
    }

    float* outp = g_part[blockIdx.y];
    int col = tx * 4;
#pragma unroll
    for (int i = 0; i < 4; i++) {
        int row = m0 + ty * 4 + i;
        if (row < GN) {
            float v0, v1, v2, v3;
            unpack2(accp[i][0], v0, v1);
            unpack2(accp[i][1], v2, v3);
            float4 o = make_float4(v0, v1, v2, v3);
            *(float4*)&outp[(size_t)row * HH + col] = o;
        }
    }
}

// ---------------- K-split reduction + bias + leaky relu -> g_hx --------------
__global__ __launch_bounds__(256) void k_reduce(const float* __restrict__ bias) {
    int idx = blockIdx.x * 256 + threadIdx.x;   // over GN*HH
    if (idx >= GN * HH) return;
    int o = idx & 63;
    float v = g_part[0][idx] + g_part[1][idx] + g_part[2][idx]
            + g_part[3][idx] + g_part[4][idx] + g_part[5][idx];
    g_hx[idx] = lrelu(v + bias[o]);
}

// ---------------- global_add_pool + head -------------------------------------
__global__ void k_pool(const void* batch) {
    int t = threadIdx.x;
    int n = blockIdx.x * 4 + (t >> 6);
    int o = t & 63;
    int g = (int)ld_idx(batch, n, g_b64);
    atomicAdd(&g_hg[g * HH + o], g_hx[(size_t)n * HH + o]);
}

__global__ void k_head(const float* __restrict__ fc1w, const float* __restrict__ fc1b,
                       const float* __restrict__ fc2w, const float* __restrict__ fc2b,
                       float* __restrict__ out) {
    int g = threadIdx.x;
    if (g >= GG) return;
    float h[64];
#pragma unroll
    for (int i = 0; i < 64; i++) h[i] = g_hg[g * 64 + i];
    float o = fc2b[0];
    for (int j = 0; j < 32; j++) {
        float s = fc1b[j];
#pragma unroll
        for (int i = 0; i < 64; i++) s = fmaf(h[i], fc1w[i * 32 + j], s);
        o = fmaf(lrelu(s), fc2w[j], o);
    }
    out[g] = o;
}

// ---------------- launch ------------------------------------------------------
extern "C" void kernel_launch(void* const* d_in, const int* in_sizes, int n_in,
                              void* d_out, int out_size) {
    const float* x     = (const float*)d_in[0];
    const void*  eidx  = d_in[1];
    const float* ea    = (const float*)d_in[2];
    const void*  batch = d_in[3];
    const float* nfc_w = (const float*)d_in[4];
    const float* nfc_b = (const float*)d_in[5];
    const float* e1w1  = (const float*)d_in[6];
    const float* e1b1  = (const float*)d_in[7];
    const float* e1w2  = (const float*)d_in[8];
    const float* e1b2  = (const float*)d_in[9];
    const float* g1root= (const float*)d_in[10];
    const float* g1bias= (const float*)d_in[11];
    const float* e2w1  = (const float*)d_in[12];
    const float* e2b1  = (const float*)d_in[13];
    const float* e2w2  = (const float*)d_in[14];
    const float* e2b2  = (const float*)d_in[15];
    const float* g2root= (const float*)d_in[16];
    const float* g2bias= (const float*)d_in[17];
    const float* fc1w  = (const float*)d_in[18];
    const float* fc1b  = (const float*)d_in[19];
    const float* fc2w  = (const float*)d_in[20];
    const float* fc2b  = (const float*)d_in[21];
    float* out = (float*)d_out;

    k_detect<<<1, 32>>>(eidx, batch);                       // launch 1
    k_zero<<<(GN + 255) / 256, 256>>>();                    // launch 2
    k_nodefc<<<GN / 4, 256>>>(x, nfc_w, nfc_b);             // launch 3
    k_hidden<<<GE / 4, 256>>>(ea, e1w1, e1b1);              // launch 4 (ncu slot)
    k_hist<<<GE / 256, 256>>>(eidx);
    k_scan<<<1, 1024>>>();
    k_fill<<<GE / 256, 256>>>(eidx);

    dim3 gemm_grid((GN + 63) / 64, KSPLIT);

    // layer 1 (k_hidden for layer 1 already launched above)
    k_prepB<<<(KTOT * HH + 255) / 256, 256>>>(e1w2, e1b2, g1root);
    k_S<<<GN, 128>>>(eidx);
    k_gemm_ks<<<gemm_grid, 256>>>();
    k_reduce<<<(GN * HH + 255) / 256, 256>>>(g1bias);

    // layer 2
    k_prepB<<<(KTOT * HH + 255) / 256, 256>>>(e2w2, e2b2, g2root);
    k_hidden<<<GE / 4, 256>>>(ea, e2w1, e2b1);
    k_S<<<GN, 128>>>(eidx);
    k_gemm_ks<<<gemm_grid, 256>>>();
    k_reduce<<<(GN * HH + 255) / 256, 256>>>(g2bias);

    k_pool<<<GN / 4, 256>>>(batch);
    k_head<<<1, 64>>>(fc1w, fc1b, fc2w, fc2b, out);
}

// round 8
// speedup vs baseline: 1.1159x; 1.1159x over previous
#include <cuda_runtime.h>
#include <cstdint>

#define GN 10000   // nodes
#define GE 64000   // edges
#define GG 64      // graphs
#define HH 64      // hidden
#define XD 128     // input feat
#define EAD 32     // edge attr dim
#define KTOT 4224  // 4096 (S outer) + 64 (sh @ B2) + 64 (h @ root)
#define KSPLIT 6
#define KSEG (KTOT / KSPLIT)      // 704
#define BK 32
#define NCHUNK_KS (KSEG / BK)     // 22
#define EB 16      // edge batch in k_S

// ---------------- scratch (static device memory; no allocs allowed) ----------
__device__ float g_hx[GN * HH];                    // node features (in-place per layer)
__device__ float g_hidden[GE * HH];                // edge MLP hidden (relu(ea@w1+b1))
__device__ float g_S[(size_t)GN * KTOT];           // per-node bilinear accumulators + sh + h
__device__ float g_Bcat[KTOT * HH];                // [w2 as 4096x64 ; B2 ; root], row-major [k][o]
__device__ float g_part[KSPLIT][GN * HH];          // K-split partial sums
__device__ int   g_cnt[GN];
__device__ int   g_off[GN + 1];
__device__ int   g_cur[GN];
__device__ int   g_sorted[GE];
__device__ float g_hg[GG * HH];
__device__ int   g_e64;                            // edge_index is int64?
__device__ int   g_b64;                            // batch is int64?

__device__ __forceinline__ long long ld_idx(const void* p, long long i, int is64) {
    return is64 ? ((const long long*)p)[i] : (long long)((const int*)p)[i];
}
__device__ __forceinline__ float lrelu(float v) { return v >= 0.f ? v : 0.01f * v; }

// ---- packed f32x2 helpers (Blackwell FFMA2; base sm_100 PTX) -----------------
__device__ __forceinline__ uint64_t pack2(float x, float y) {
    uint64_t r;
    asm("mov.b64 %0, {%1, %2};" : "=l"(r) : "f"(x), "f"(y));
    return r;
}
__device__ __forceinline__ void unpack2(uint64_t v, float& x, float& y) {
    asm("mov.b64 {%0, %1}, %2;" : "=f"(x), "=f"(y) : "l"(v));
}
__device__ __forceinline__ void ffma2(uint64_t& acc, uint64_t a, uint64_t b) {
    asm("fma.rn.f32x2 %0, %1, %2, %0;" : "+l"(acc) : "l"(a), "l"(b));
}

// ---------------- dtype detection (parallel, one warp) -----------------------
__global__ void k_detect(const void* eidx, const void* batch) {
    int t = threadIdx.x;  // 32 threads
    const long long* p = (const long long*)eidx;
    bool ok = true;
#pragma unroll
    for (int j = 0; j < 4; j++) {
        long long v = p[t + j * 32];
        ok &= (v >= 0 && v < GN);
    }
    unsigned e_ok = __all_sync(0xFFFFFFFFu, ok);
    const long long* b = (const long long*)batch;
    bool okb = true;
#pragma unroll
    for (int j = 0; j < 2; j++) {
        long long v = b[GN / 2 - 64 + t + j * 32];
        okb &= (v >= 0 && v < GG);
    }
    unsigned b_ok = __all_sync(0xFFFFFFFFu, okb);
    if (t == 0) { g_e64 = e_ok ? 1 : 0; g_b64 = b_ok ? 1 : 0; }
}

__global__ void k_zero() {
    int i = blockIdx.x * 256 + threadIdx.x;
    if (i < GN) { g_cnt[i] = 0; g_cur[i] = 0; }
    if (i < GG * HH) g_hg[i] = 0.f;
}

// ---------------- node encoder: hx = lrelu(x @ nfc_w + nfc_b) ----------------
// 16 nodes/block; weight matrix staged once in smem (32KB) and reused.
__global__ __launch_bounds__(256) void k_nodefc(const float* __restrict__ x,
                                                const float* __restrict__ w,
                                                const float* __restrict__ b) {
    __shared__ float ws[XD * HH];       // 32 KB
    __shared__ float xs[16][XD];        // 8 KB
    int n0 = blockIdx.x * 16;
    int t = threadIdx.x;
#pragma unroll
    for (int i = 0; i < XD * HH / 256; i++)          // 32 iters, coalesced
        ws[t + i * 256] = w[t + i * 256];
#pragma unroll
    for (int i = 0; i < 16 * XD / 256; i++) {        // 8 iters
        int idx = t + i * 256;
        xs[idx >> 7][idx & 127] = x[(size_t)(n0 + (idx >> 7)) * XD + (idx & 127)];
    }
    __syncthreads();
    int ln = t >> 4;            // 0..15 node
    int o = (t & 15) * 4;       // 4 outputs
    float4 acc = *(const float4*)&b[o];
    for (int k = 0; k < XD; k++) {
        float c = xs[ln][k];
        float4 wv = *(const float4*)&ws[k * HH + o];
        acc.x = fmaf(c, wv.x, acc.x);
        acc.y = fmaf(c, wv.y, acc.y);
        acc.z = fmaf(c, wv.z, acc.z);
        acc.w = fmaf(c, wv.w, acc.w);
    }
    float4 r = make_float4(lrelu(acc.x), lrelu(acc.y), lrelu(acc.z), lrelu(acc.w));
    *(float4*)&g_hx[(size_t)(n0 + ln) * HH + o] = r;
}

// ---------------- edge MLP hidden: relu(ea @ w1 + b1) ------------------------
// 32 edges/block; w1 (8KB) + edge attrs staged in smem.
__global__ __launch_bounds__(256) void k_hidden(const float* __restrict__ ea,
                                                const float* __restrict__ w1,
                                                const float* __restrict__ b1) {
    __shared__ float w1s[EAD * HH];     // 8 KB
    __shared__ float eas[32][EAD + 1];  // 4.1 KB
    int e0 = blockIdx.x * 32;
    int t = threadIdx.x;
#pragma unroll
    for (int i = 0; i < EAD * HH / 256; i++)         // 8 iters
        w1s[t + i * 256] = w1[t + i * 256];
#pragma unroll
    for (int i = 0; i < 32 * EAD / 256; i++) {       // 4 iters
        int idx = t + i * 256;
        eas[idx >> 5][idx & 31] = ea[(size_t)(e0 + (idx >> 5)) * EAD + (idx & 31)];
    }
    __syncthreads();
    int le = t >> 3;            // 0..31 edge
    int o = (t & 7) * 8;        // 8 outputs
    float4 a0 = *(const float4*)&b1[o];
    float4 a1 = *(const float4*)&b1[o + 4];
#pragma unroll
    for (int k = 0; k < EAD; k++) {
        float c = eas[le][k];
        float4 w0 = *(const float4*)&w1s[k * HH + o];
        float4 w1v = *(const float4*)&w1s[k * HH + o + 4];
        a0.x = fmaf(c, w0.x, a0.x); a0.y = fmaf(c, w0.y, a0.y);
        a0.z = fmaf(c, w0.z, a0.z); a0.w = fmaf(c, w0.w, a0.w);
        a1.x = fmaf(c, w1v.x, a1.x); a1.y = fmaf(c, w1v.y, a1.y);
        a1.z = fmaf(c, w1v.z, a1.z); a1.w = fmaf(c, w1v.w, a1.w);
    }
    float* outp = &g_hidden[(size_t)(e0 + le) * HH + o];
    *(float4*)&outp[0] = make_float4(fmaxf(a0.x, 0.f), fmaxf(a0.y, 0.f),
                                     fmaxf(a0.z, 0.f), fmaxf(a0.w, 0.f));
    *(float4*)&outp[4] = make_float4(fmaxf(a1.x, 0.f), fmaxf(a1.y, 0.f),
                                     fmaxf(a1.z, 0.f), fmaxf(a1.w, 0.f));
}

// ---------------- CSR build (counting sort by dst, deterministic) ------------
__global__ void k_hist(const void* eidx) {
    int e = blockIdx.x * 256 + threadIdx.x;
    if (e >= GE) return;
    int d = (int)ld_idx(eidx, (long long)GE + e, g_e64);
    atomicAdd(&g_cnt[d], 1);
}

__global__ __launch_bounds__(1024) void k_scan() {
    __shared__ int part[1024];
    const int C = 10;
    int t = threadIdx.x;
    int base = t * C;
    int loc[C];
    int s = 0;
#pragma unroll
    for (int j = 0; j < C; j++) {
        int idx = base + j;
        int c = (idx < GN) ? g_cnt[idx] : 0;
        loc[j] = s;
        s += c;
    }
    part[t] = s;
    __syncthreads();
    for (int off = 1; off < 1024; off <<= 1) {
        int v = (t >= off) ? part[t - off] : 0;
        __syncthreads();
        part[t] += v;
        __syncthreads();
    }
    int pre = part[t] - s;  // exclusive prefix
#pragma unroll
    for (int j = 0; j < C; j++) {
        int idx = base + j;
        if (idx <= GN) g_off[idx] = pre + loc[j];
    }
}

__global__ void k_fill(const void* eidx) {
    int e = blockIdx.x * 256 + threadIdx.x;
    if (e >= GE) return;
    int d = (int)ld_idx(eidx, (long long)GE + e, g_e64);
    int pos = g_off[d] + atomicAdd(&g_cur[d], 1);
    g_sorted[pos] = e;
}

__global__ void k_sortnode() {
    int n = blockIdx.x * 128 + threadIdx.x;
    if (n >= GN) return;
    int b = g_off[n], e = g_off[n + 1];
    for (int i = b + 1; i < e; i++) {
        int v = g_sorted[i];
        int j = i - 1;
        while (j >= b && g_sorted[j] > v) { g_sorted[j + 1] = g_sorted[j]; j--; }
        g_sorted[j + 1] = v;
    }
}

// ---------------- B matrix concat: [w2(4096x64); B2(64x64); root(64x64)] -----
__global__ void k_prepB(const float* __restrict__ w2, const float* __restrict__ b2,
                        const float* __restrict__ root) {
    int idx = blockIdx.x * 256 + threadIdx.x;
    if (idx >= KTOT * HH) return;
    int r = idx >> 6, o = idx & 63;
    float v;
    if (r < 4096)       v = w2[idx];                     // (k*64+i)*64+o == k*4096+i*64+o
    else if (r < 4160)  v = b2[(r - 4096) * HH + o];
    else                v = root[(r - 4160) * HH + o];
    g_Bcat[idx] = v;
}

// ---------------- per-node S row: batched outer-product accumulation ---------
__global__ __launch_bounds__(128) void k_S(const void* eidx) {
    int n = blockIdx.x;
    int t = threadIdx.x;
    int k = t >> 1, half = t & 1;
    __shared__ float hid_s[EB][64];
    __shared__ float hsrc_s[EB][68];
    float acc[32];
#pragma unroll
    for (int q = 0; q < 32; q++) acc[q] = 0.f;
    float shacc = 0.f;
    int beg = g_off[n], end = g_off[n + 1];
    int is64 = g_e64;
    for (int b0 = beg; b0 < end; b0 += EB) {
        int nb = min(EB, end - b0);
        __syncthreads();   // previous batch's smem readers done
        for (int idx = t; idx < nb * 16; idx += 128) {
            int le = idx >> 4, q = idx & 15;
            int e = g_sorted[b0 + le];
            long long s = ld_idx(eidx, e, is64);
            *(float4*)&hid_s[le][q * 4]  = *(const float4*)&g_hidden[(size_t)e * HH + q * 4];
            *(float4*)&hsrc_s[le][q * 4] = *(const float4*)&g_hx[(size_t)s * HH + q * 4];
        }
        __syncthreads();
        for (int le = 0; le < nb; le++) {
            float c = hid_s[le][k];
            const float4* hp = (const float4*)&hsrc_s[le][half * 32];
#pragma unroll
            for (int q4 = 0; q4 < 8; q4++) {
                float4 h = hp[q4];
                acc[q4 * 4 + 0] = fmaf(c, h.x, acc[q4 * 4 + 0]);
                acc[q4 * 4 + 1] = fmaf(c, h.y, acc[q4 * 4 + 1]);
                acc[q4 * 4 + 2] = fmaf(c, h.z, acc[q4 * 4 + 2]);
                acc[q4 * 4 + 3] = fmaf(c, h.w, acc[q4 * 4 + 3]);
            }
        }
        if (t < 64) {
            for (int le = 0; le < nb; le++) shacc += hsrc_s[le][t];
        }
    }
    size_t base = (size_t)n * KTOT;
#pragma unroll
    for (int q = 0; q < 32; q += 4) {
        float4 v = make_float4(acc[q], acc[q + 1], acc[q + 2], acc[q + 3]);
        *(float4*)&g_S[base + k * 64 + half * 32 + q] = v;
    }
    if (t < 64) g_S[base + 4096 + t] = shacc;
    else        g_S[base + 4160 + (t - 64)] = g_hx[(size_t)n * HH + (t - 64)];
}

// ---------------- GEMM (K-split): g_part[ks] = S[:, ks-seg] @ Bcat[ks-seg, :]
// (R6-proven version: pack2 in inner loop)
__global__ __launch_bounds__(256) void k_gemm_ks() {
    __shared__ float As[BK][68];   // [kk][m]
    __shared__ float Bs[BK][64];   // [kk][o]
    int t = threadIdx.x;
    int m0 = blockIdx.x * 64;
    int kbase = blockIdx.y * KSEG;
    int tx = t & 15, ty = t >> 4;

    uint64_t accp[4][2];
#pragma unroll
    for (int i = 0; i < 4; i++) { accp[i][0] = 0ull; accp[i][1] = 0ull; }

    int ar[2], ac4[2], aok[2];
#pragma unroll
    for (int q = 0; q < 2; q++) {
        int idx = t + 256 * q;
        ar[q] = idx >> 3;
        ac4[q] = idx & 7;
        aok[q] = (m0 + ar[q]) < GN;
    }
    float4 ra[2], rb[2];

#pragma unroll
    for (int q = 0; q < 2; q++) {
        ra[q] = aok[q] ? *(const float4*)&g_S[(size_t)(m0 + ar[q]) * KTOT + kbase + ac4[q] * 4]
                       : make_float4(0.f, 0.f, 0.f, 0.f);
        int idx = t + 256 * q;
        rb[q] = *(const float4*)&g_Bcat[(kbase + (idx >> 4)) * 64 + (idx & 15) * 4];
    }

    for (int c = 0; c < NCHUNK_KS; c++) {
        __syncthreads();
#pragma unroll
        for (int q = 0; q < 2; q++) {
            int kb = ac4[q] * 4;
            As[kb + 0][ar[q]] = ra[q].x;
            As[kb + 1][ar[q]] = ra[q].y;
            As[kb + 2][ar[q]] = ra[q].z;
            As[kb + 3][ar[q]] = ra[q].w;
            int idx = t + 256 * q;
            *(float4*)&Bs[idx >> 4][(idx & 15) * 4] = rb[q];
        }
        __syncthreads();

        if (c + 1 < NCHUNK_KS) {
            int k0 = kbase + (c + 1) * BK;
#pragma unroll
            for (int q = 0; q < 2; q++) {
                ra[q] = aok[q] ? *(const float4*)&g_S[(size_t)(m0 + ar[q]) * KTOT + k0 + ac4[q] * 4]
                               : make_float4(0.f, 0.f, 0.f, 0.f);
                int idx = t + 256 * q;
                rb[q] = *(const float4*)&g_Bcat[(k0 + (idx >> 4)) * 64 + (idx & 15) * 4];
            }
        }

#pragma unroll
        for (int kk = 0; kk < BK; kk++) {
            float4 a = *(const float4*)&As[kk][ty * 4];
            float4 b = *(const float4*)&Bs[kk][tx * 4];
            uint64_t b01 = pack2(b.x, b.y);
            uint64_t b23 = pack2(b.z, b.w);
            uint64_t a0 = pack2(a.x, a.x);
            uint64_t a1 = pack2(a.y, a.y);
            uint64_t a2 = pack2(a.z, a.z);
            uint64_t a3 = pack2(a.w, a.w);
            ffma2(accp[0][0], a0, b01); ffma2(accp[0][1], a0, b23);
            ffma2(accp[1][0], a1, b01); ffma2(accp[1][1], a1, b23);
            ffma2(accp[2][0], a2, b01); ffma2(accp[2][1], a2, b23);
            ffma2(accp[3][0], a3, b01); ffma2(accp[3][1], a3, b23);
        }
    }

    float* outp = g_part[blockIdx.y];
    int col = tx * 4;
#pragma unroll
    for (int i = 0; i < 4; i++) {
        int row = m0 + ty * 4 + i;
        if (row < GN) {
            float v0, v1, v2, v3;
            unpack2(accp[i][0], v0, v1);
            unpack2(accp[i][1], v2, v3);
            float4 o = make_float4(v0, v1, v2, v3);
            *(float4*)&outp[(size_t)row * HH + col] = o;
        }
    }
}

// ---------------- K-split reduction + bias + leaky relu -> g_hx --------------
__global__ __launch_bounds__(256) void k_reduce(const float* __restrict__ bias) {
    int idx = blockIdx.x * 256 + threadIdx.x;   // over GN*HH
    if (idx >= GN * HH) return;
    int o = idx & 63;
    float v = g_part[0][idx] + g_part[1][idx] + g_part[2][idx]
            + g_part[3][idx] + g_part[4][idx] + g_part[5][idx];
    g_hx[idx] = lrelu(v + bias[o]);
}

// ---------------- global_add_pool + head -------------------------------------
__global__ void k_pool(const void* batch) {
    int t = threadIdx.x;
    int n = blockIdx.x * 4 + (t >> 6);
    int o = t & 63;
    int g = (int)ld_idx(batch, n, g_b64);
    atomicAdd(&g_hg[g * HH + o], g_hx[(size_t)n * HH + o]);
}

__global__ void k_head(const float* __restrict__ fc1w, const float* __restrict__ fc1b,
                       const float* __restrict__ fc2w, const float* __restrict__ fc2b,
                       float* __restrict__ out) {
    int g = threadIdx.x;
    if (g >= GG) return;
    float h[64];
#pragma unroll
    for (int i = 0; i < 64; i++) h[i] = g_hg[g * 64 + i];
    float o = fc2b[0];
    for (int j = 0; j < 32; j++) {
        float s = fc1b[j];
#pragma unroll
        for (int i = 0; i < 64; i++) s = fmaf(h[i], fc1w[i * 32 + j], s);
        o = fmaf(lrelu(s), fc2w[j], o);
    }
    out[g] = o;
}

// ---------------- launch ------------------------------------------------------
extern "C" void kernel_launch(void* const* d_in, const int* in_sizes, int n_in,
                              void* d_out, int out_size) {
    const float* x     = (const float*)d_in[0];
    const void*  eidx  = d_in[1];
    const float* ea    = (const float*)d_in[2];
    const void*  batch = d_in[3];
    const float* nfc_w = (const float*)d_in[4];
    const float* nfc_b = (const float*)d_in[5];
    const float* e1w1  = (const float*)d_in[6];
    const float* e1b1  = (const float*)d_in[7];
    const float* e1w2  = (const float*)d_in[8];
    const float* e1b2  = (const float*)d_in[9];
    const float* g1root= (const float*)d_in[10];
    const float* g1bias= (const float*)d_in[11];
    const float* e2w1  = (const float*)d_in[12];
    const float* e2b1  = (const float*)d_in[13];
    const float* e2w2  = (const float*)d_in[14];
    const float* e2b2  = (const float*)d_in[15];
    const float* g2root= (const float*)d_in[16];
    const float* g2bias= (const float*)d_in[17];
    const float* fc1w  = (const float*)d_in[18];
    const float* fc1b  = (const float*)d_in[19];
    const float* fc2w  = (const float*)d_in[20];
    const float* fc2b  = (const float*)d_in[21];
    float* out = (float*)d_out;

    k_detect<<<1, 32>>>(eidx, batch);                       // launch 1
    k_zero<<<(GN + 255) / 256, 256>>>();                    // launch 2
    k_nodefc<<<GN / 16, 256>>>(x, nfc_w, nfc_b);            // launch 3
    k_hidden<<<GE / 32, 256>>>(ea, e1w1, e1b1);             // launch 4 (ncu slot)
    k_hist<<<GE / 256, 256>>>(eidx);
    k_scan<<<1, 1024>>>();
    k_fill<<<GE / 256, 256>>>(eidx);
    k_sortnode<<<(GN + 127) / 128, 128>>>();

    dim3 gemm_grid((GN + 63) / 64, KSPLIT);

    // layer 1 (k_hidden for layer 1 already launched above)
    k_prepB<<<(KTOT * HH + 255) / 256, 256>>>(e1w2, e1b2, g1root);
    k_S<<<GN, 128>>>(eidx);
    k_gemm_ks<<<gemm_grid, 256>>>();
    k_reduce<<<(GN * HH + 255) / 256, 256>>>(g1bias);

    // layer 2
    k_prepB<<<(KTOT * HH + 255) / 256, 256>>>(e2w2, e2b2, g2root);
    k_hidden<<<GE / 32, 256>>>(ea, e2w1, e2b1);
    k_S<<<GN, 128>>>(eidx);
    k_gemm_ks<<<gemm_grid, 256>>>();
    k_reduce<<<(GN * HH + 255) / 256, 256>>>(g2bias);

    k_pool<<<GN / 4, 256>>>(batch);
    k_head<<<1, 64>>>(fc1w, fc1b, fc2w, fc2b, out);
}

// round 9
// speedup vs baseline: 1.1929x; 1.0690x over previous
#include <cuda_runtime.h>
#include <cstdint>

#define GN 10000   // nodes
#define GE 64000   // edges
#define GG 64      // graphs
#define HH 64      // hidden
#define XD 128     // input feat
#define EAD 32     // edge attr dim
#define KTOT 4224  // 4096 (S outer) + 64 (sh @ B2) + 64 (h @ root)
#define KSPLIT 6
#define KSEG (KTOT / KSPLIT)      // 704
#define BK 32
#define NCHUNK_KS (KSEG / BK)     // 22
#define EB 16      // edge batch in k_S

// ---------------- scratch (static device memory; no allocs allowed) ----------
__device__ float g_hx[GN * HH];                    // node features (in-place per layer)
__device__ float g_hidden[GE * HH];                // edge MLP hidden (relu(ea@w1+b1))
__device__ float g_S[(size_t)GN * KTOT];           // per-node bilinear accumulators + sh + h
__device__ float g_Bcat[KTOT * HH];                // [w2 as 4096x64 ; B2 ; root], row-major [k][o]
__device__ float g_part[KSPLIT][GN * HH];          // K-split partial sums
__device__ int   g_cnt[GN];
__device__ int   g_off[GN + 1];
__device__ int   g_cur[GN];
__device__ int   g_sorted[GE];
__device__ float g_hg[GG * HH];
__device__ int   g_e64;                            // edge_index is int64?
__device__ int   g_b64;                            // batch is int64?

__device__ __forceinline__ long long ld_idx(const void* p, long long i, int is64) {
    return is64 ? ((const long long*)p)[i] : (long long)((const int*)p)[i];
}
__device__ __forceinline__ float lrelu(float v) { return v >= 0.f ? v : 0.01f * v; }

// ---- packed f32x2 helpers (Blackwell FFMA2; base sm_100 PTX) -----------------
__device__ __forceinline__ uint64_t pack2(float x, float y) {
    uint64_t r;
    asm("mov.b64 %0, {%1, %2};" : "=l"(r) : "f"(x), "f"(y));
    return r;
}
__device__ __forceinline__ void unpack2(uint64_t v, float& x, float& y) {
    asm("mov.b64 {%0, %1}, %2;" : "=f"(x), "=f"(y) : "l"(v));
}
__device__ __forceinline__ void ffma2(uint64_t& acc, uint64_t a, uint64_t b) {
    asm("fma.rn.f32x2 %0, %1, %2, %0;" : "+l"(acc) : "l"(a), "l"(b));
}

// ---------------- dtype detection (parallel, one warp) -----------------------
__global__ void k_detect(const void* eidx, const void* batch) {
    int t = threadIdx.x;  // 32 threads
    const long long* p = (const long long*)eidx;
    bool ok = true;
#pragma unroll
    for (int j = 0; j < 4; j++) {
        long long v = p[t + j * 32];
        ok &= (v >= 0 && v < GN);
    }
    unsigned e_ok = __all_sync(0xFFFFFFFFu, ok);
    const long long* b = (const long long*)batch;
    bool okb = true;
#pragma unroll
    for (int j = 0; j < 2; j++) {
        long long v = b[GN / 2 - 64 + t + j * 32];
        okb &= (v >= 0 && v < GG);
    }
    unsigned b_ok = __all_sync(0xFFFFFFFFu, okb);
    if (t == 0) { g_e64 = e_ok ? 1 : 0; g_b64 = b_ok ? 1 : 0; }
}

__global__ void k_zero() {
    int i = blockIdx.x * 256 + threadIdx.x;
    if (i < GN) { g_cnt[i] = 0; g_cur[i] = 0; }
    if (i < GG * HH) g_hg[i] = 0.f;
}

// ---------------- node encoder: hx = lrelu(x @ nfc_w + nfc_b) ----------------
// 16 nodes/block; weight matrix staged once in smem (32KB) and reused.
__global__ __launch_bounds__(256) void k_nodefc(const float* __restrict__ x,
                                                const float* __restrict__ w,
                                                const float* __restrict__ b) {
    __shared__ float ws[XD * HH];       // 32 KB
    __shared__ float xs[16][XD];        // 8 KB
    int n0 = blockIdx.x * 16;
    int t = threadIdx.x;
#pragma unroll
    for (int i = 0; i < XD * HH / 256; i++)          // 32 iters, coalesced
        ws[t + i * 256] = w[t + i * 256];
#pragma unroll
    for (int i = 0; i < 16 * XD / 256; i++) {        // 8 iters
        int idx = t + i * 256;
        xs[idx >> 7][idx & 127] = x[(size_t)(n0 + (idx >> 7)) * XD + (idx & 127)];
    }
    __syncthreads();
    int ln = t >> 4;            // 0..15 node
    int o = (t & 15) * 4;       // 4 outputs
    float4 acc = *(const float4*)&b[o];
    for (int k = 0; k < XD; k++) {
        float c = xs[ln][k];
        float4 wv = *(const float4*)&ws[k * HH + o];
        acc.x = fmaf(c, wv.x, acc.x);
        acc.y = fmaf(c, wv.y, acc.y);
        acc.z = fmaf(c, wv.z, acc.z);
        acc.w = fmaf(c, wv.w, acc.w);
    }
    float4 r = make_float4(lrelu(acc.x), lrelu(acc.y), lrelu(acc.z), lrelu(acc.w));
    *(float4*)&g_hx[(size_t)(n0 + ln) * HH + o] = r;
}

// ---------------- edge MLP hidden: relu(ea @ w1 + b1) ------------------------
// 64 edges/block, register-blocked: each thread computes 4 edges x 4 outputs.
// ea staged TRANSPOSED (easT[k][le], stride 68 -> 16B-aligned rows) so the
// inner loop is 2x LDS.128 + 16 FMA per k  (2 B/FMA vs 8 B/FMA before).
__global__ __launch_bounds__(256) void k_hidden(const float* __restrict__ ea,
                                                const float* __restrict__ w1,
                                                const float* __restrict__ b1) {
    __shared__ float w1s[EAD * HH];     // 8 KB
    __shared__ float easT[EAD][68];     // transposed edge attrs, 8.5 KB
    int e0 = blockIdx.x * 64;
    int t = threadIdx.x;
#pragma unroll
    for (int i = 0; i < EAD * HH / 256; i++)         // 8 iters, coalesced
        w1s[t + i * 256] = w1[t + i * 256];
#pragma unroll
    for (int q = 0; q < 2; q++) {                    // 64 edges x 32 attrs
        int idx = t + q * 256;
        int le = idx >> 3, kq = (idx & 7) * 4;
        float4 v = *(const float4*)&ea[(size_t)(e0 + le) * EAD + kq];
        easT[kq + 0][le] = v.x;
        easT[kq + 1][le] = v.y;
        easT[kq + 2][le] = v.z;
        easT[kq + 3][le] = v.w;
    }
    __syncthreads();
    int eq = (t & 15) * 4;      // edge quad base (0..60)
    int og = (t >> 4) * 4;      // output quad base (0..60)
    float4 bv = *(const float4*)&b1[og];
    float4 acc0 = bv, acc1 = bv, acc2 = bv, acc3 = bv;
#pragma unroll
    for (int k = 0; k < EAD; k++) {
        float4 cv = *(const float4*)&easT[k][eq];
        float4 wv = *(const float4*)&w1s[k * HH + og];
        acc0.x = fmaf(cv.x, wv.x, acc0.x); acc0.y = fmaf(cv.x, wv.y, acc0.y);
        acc0.z = fmaf(cv.x, wv.z, acc0.z); acc0.w = fmaf(cv.x, wv.w, acc0.w);
        acc1.x = fmaf(cv.y, wv.x, acc1.x); acc1.y = fmaf(cv.y, wv.y, acc1.y);
        acc1.z = fmaf(cv.y, wv.z, acc1.z); acc1.w = fmaf(cv.y, wv.w, acc1.w);
        acc2.x = fmaf(cv.z, wv.x, acc2.x); acc2.y = fmaf(cv.z, wv.y, acc2.y);
        acc2.z = fmaf(cv.z, wv.z, acc2.z); acc2.w = fmaf(cv.z, wv.w, acc2.w);
        acc3.x = fmaf(cv.w, wv.x, acc3.x); acc3.y = fmaf(cv.w, wv.y, acc3.y);
        acc3.z = fmaf(cv.w, wv.z, acc3.z); acc3.w = fmaf(cv.w, wv.w, acc3.w);
    }
    float4 r;
    r = make_float4(fmaxf(acc0.x, 0.f), fmaxf(acc0.y, 0.f), fmaxf(acc0.z, 0.f), fmaxf(acc0.w, 0.f));
    *(float4*)&g_hidden[(size_t)(e0 + eq + 0) * HH + og] = r;
    r = make_float4(fmaxf(acc1.x, 0.f), fmaxf(acc1.y, 0.f), fmaxf(acc1.z, 0.f), fmaxf(acc1.w, 0.f));
    *(float4*)&g_hidden[(size_t)(e0 + eq + 1) * HH + og] = r;
    r = make_float4(fmaxf(acc2.x, 0.f), fmaxf(acc2.y, 0.f), fmaxf(acc2.z, 0.f), fmaxf(acc2.w, 0.f));
    *(float4*)&g_hidden[(size_t)(e0 + eq + 2) * HH + og] = r;
    r = make_float4(fmaxf(acc3.x, 0.f), fmaxf(acc3.y, 0.f), fmaxf(acc3.z, 0.f), fmaxf(acc3.w, 0.f));
    *(float4*)&g_hidden[(size_t)(e0 + eq + 3) * HH + og] = r;
}

// ---------------- CSR build (counting sort by dst, deterministic) ------------
__global__ void k_hist(const void* eidx) {
    int e = blockIdx.x * 256 + threadIdx.x;
    if (e >= GE) return;
    int d = (int)ld_idx(eidx, (long long)GE + e, g_e64);
    atomicAdd(&g_cnt[d], 1);
}

__global__ __launch_bounds__(1024) void k_scan() {
    __shared__ int part[1024];
    const int C = 10;
    int t = threadIdx.x;
    int base = t * C;
    int loc[C];
    int s = 0;
#pragma unroll
    for (int j = 0; j < C; j++) {
        int idx = base + j;
        int c = (idx < GN) ? g_cnt[idx] : 0;
        loc[j] = s;
        s += c;
    }
    part[t] = s;
    __syncthreads();
    for (int off = 1; off < 1024; off <<= 1) {
        int v = (t >= off) ? part[t - off] : 0;
        __syncthreads();
        part[t] += v;
        __syncthreads();
    }
    int pre = part[t] - s;  // exclusive prefix
#pragma unroll
    for (int j = 0; j < C; j++) {
        int idx = base + j;
        if (idx <= GN) g_off[idx] = pre + loc[j];
    }
}

__global__ void k_fill(const void* eidx) {
    int e = blockIdx.x * 256 + threadIdx.x;
    if (e >= GE) return;
    int d = (int)ld_idx(eidx, (long long)GE + e, g_e64);
    int pos = g_off[d] + atomicAdd(&g_cur[d], 1);
    g_sorted[pos] = e;
}

__global__ void k_sortnode() {
    int n = blockIdx.x * 128 + threadIdx.x;
    if (n >= GN) return;
    int b = g_off[n], e = g_off[n + 1];
    for (int i = b + 1; i < e; i++) {
        int v = g_sorted[i];
        int j = i - 1;
        while (j >= b && g_sorted[j] > v) { g_sorted[j + 1] = g_sorted[j]; j--; }
        g_sorted[j + 1] = v;
    }
}

// ---------------- B matrix concat: [w2(4096x64); B2(64x64); root(64x64)] -----
__global__ void k_prepB(const float* __restrict__ w2, const float* __restrict__ b2,
                        const float* __restrict__ root) {
    int idx = blockIdx.x * 256 + threadIdx.x;
    if (idx >= KTOT * HH) return;
    int r = idx >> 6, o = idx & 63;
    float v;
    if (r < 4096)       v = w2[idx];                     // (k*64+i)*64+o == k*4096+i*64+o
    else if (r < 4160)  v = b2[(r - 4096) * HH + o];
    else                v = root[(r - 4160) * HH + o];
    g_Bcat[idx] = v;
}

// ---------------- per-node S row: batched outer-product accumulation ---------
__global__ __launch_bounds__(128) void k_S(const void* eidx) {
    int n = blockIdx.x;
    int t = threadIdx.x;
    int k = t >> 1, half = t & 1;
    __shared__ float hid_s[EB][64];
    __shared__ float hsrc_s[EB][68];
    float acc[32];
#pragma unroll
    for (int q = 0; q < 32; q++) acc[q] = 0.f;
    float shacc = 0.f;
    int beg = g_off[n], end = g_off[n + 1];
    int is64 = g_e64;
    for (int b0 = beg; b0 < end; b0 += EB) {
        int nb = min(EB, end - b0);
        __syncthreads();   // previous batch's smem readers done
        for (int idx = t; idx < nb * 16; idx += 128) {
            int le = idx >> 4, q = idx & 15;
            int e = g_sorted[b0 + le];
            long long s = ld_idx(eidx, e, is64);
            *(float4*)&hid_s[le][q * 4]  = *(const float4*)&g_hidden[(size_t)e * HH + q * 4];
            *(float4*)&hsrc_s[le][q * 4] = *(const float4*)&g_hx[(size_t)s * HH + q * 4];
        }
        __syncthreads();
        for (int le = 0; le < nb; le++) {
            float c = hid_s[le][k];
            const float4* hp = (const float4*)&hsrc_s[le][half * 32];
#pragma unroll
            for (int q4 = 0; q4 < 8; q4++) {
                float4 h = hp[q4];
                acc[q4 * 4 + 0] = fmaf(c, h.x, acc[q4 * 4 + 0]);
                acc[q4 * 4 + 1] = fmaf(c, h.y, acc[q4 * 4 + 1]);
                acc[q4 * 4 + 2] = fmaf(c, h.z, acc[q4 * 4 + 2]);
                acc[q4 * 4 + 3] = fmaf(c, h.w, acc[q4 * 4 + 3]);
            }
        }
        if (t < 64) {
            for (int le = 0; le < nb; le++) shacc += hsrc_s[le][t];
        }
    }
    size_t base = (size_t)n * KTOT;
#pragma unroll
    for (int q = 0; q < 32; q += 4) {
        float4 v = make_float4(acc[q], acc[q + 1], acc[q + 2], acc[q + 3]);
        *(float4*)&g_S[base + k * 64 + half * 32 + q] = v;
    }
    if (t < 64) g_S[base + 4096 + t] = shacc;
    else        g_S[base + 4160 + (t - 64)] = g_hx[(size_t)n * HH + (t - 64)];
}

// ---------------- GEMM (K-split): g_part[ks] = S[:, ks-seg] @ Bcat[ks-seg, :]
// (R6-proven version: pack2 in inner loop)
__global__ __launch_bounds__(256) void k_gemm_ks() {
    __shared__ float As[BK][68];   // [kk][m]
    __shared__ float Bs[BK][64];   // [kk][o]
    int t = threadIdx.x;
    int m0 = blockIdx.x * 64;
    int kbase = blockIdx.y * KSEG;
    int tx = t & 15, ty = t >> 4;

    uint64_t accp[4][2];
#pragma unroll
    for (int i = 0; i < 4; i++) { accp[i][0] = 0ull; accp[i][1] = 0ull; }

    int ar[2], ac4[2], aok[2];
#pragma unroll
    for (int q = 0; q < 2; q++) {
        int idx = t + 256 * q;
        ar[q] = idx >> 3;
        ac4[q] = idx & 7;
        aok[q] = (m0 + ar[q]) < GN;
    }
    float4 ra[2], rb[2];

#pragma unroll
    for (int q = 0; q < 2; q++) {
        ra[q] = aok[q] ? *(const float4*)&g_S[(size_t)(m0 + ar[q]) * KTOT + kbase + ac4[q] * 4]
                       : make_float4(0.f, 0.f, 0.f, 0.f);
        int idx = t + 256 * q;
        rb[q] = *(const float4*)&g_Bcat[(kbase + (idx >> 4)) * 64 + (idx & 15) * 4];
    }

    for (int c = 0; c < NCHUNK_KS; c++) {
        __syncthreads();
#pragma unroll
        for (int q = 0; q < 2; q++) {
            int kb = ac4[q] * 4;
            As[kb + 0][ar[q]] = ra[q].x;
            As[kb + 1][ar[q]] = ra[q].y;
            As[kb + 2][ar[q]] = ra[q].z;
            As[kb + 3][ar[q]] = ra[q].w;
            int idx = t + 256 * q;
            *(float4*)&Bs[idx >> 4][(idx & 15) * 4] = rb[q];
        }
        __syncthreads();

        if (c + 1 < NCHUNK_KS) {
            int k0 = kbase + (c + 1) * BK;
#pragma unroll
            for (int q = 0; q < 2; q++) {
                ra[q] = aok[q] ? *(const float4*)&g_S[(size_t)(m0 + ar[q]) * KTOT + k0 + ac4[q] * 4]
                               : make_float4(0.f, 0.f, 0.f, 0.f);
                int idx = t + 256 * q;
                rb[q] = *(const float4*)&g_Bcat[(k0 + (idx >> 4)) * 64 + (idx & 15) * 4];
            }
        }

#pragma unroll
        for (int kk = 0; kk < BK; kk++) {
            float4 a = *(const float4*)&As[kk][ty * 4];
            float4 b = *(const float4*)&Bs[kk][tx * 4];
            uint64_t b01 = pack2(b.x, b.y);
            uint64_t b23 = pack2(b.z, b.w);
            uint64_t a0 = pack2(a.x, a.x);
            uint64_t a1 = pack2(a.y, a.y);
            uint64_t a2 = pack2(a.z, a.z);
            uint64_t a3 = pack2(a.w, a.w);
            ffma2(accp[0][0], a0, b01); ffma2(accp[0][1], a0, b23);
            ffma2(accp[1][0], a1, b01); ffma2(accp[1][1], a1, b23);
            ffma2(accp[2][0], a2, b01); ffma2(accp[2][1], a2, b23);
            ffma2(accp[3][0], a3, b01); ffma2(accp[3][1], a3, b23);
        }
    }

    float* outp = g_part[blockIdx.y];
    int col = tx * 4;
#pragma unroll
    for (int i = 0; i < 4; i++) {
        int row = m0 + ty * 4 + i;
        if (row < GN) {
            float v0, v1, v2, v3;
            unpack2(accp[i][0], v0, v1);
            unpack2(accp[i][1], v2, v3);
            float4 o = make_float4(v0, v1, v2, v3);
            *(float4*)&outp[(size_t)row * HH + col] = o;
        }
    }
}

// ---------------- K-split reduction + bias + leaky relu -> g_hx --------------
__global__ __launch_bounds__(256) void k_reduce(const float* __restrict__ bias) {
    int idx = blockIdx.x * 256 + threadIdx.x;   // over GN*HH
    if (idx >= GN * HH) return;
    int o = idx & 63;
    float v = g_part[0][idx] + g_part[1][idx] + g_part[2][idx]
            + g_part[3][idx] + g_part[4][idx] + g_part[5][idx];
    g_hx[idx] = lrelu(v + bias[o]);
}

// ---------------- global_add_pool + head -------------------------------------
__global__ void k_pool(const void* batch) {
    int t = threadIdx.x;
    int n = blockIdx.x * 4 + (t >> 6);
    int o = t & 63;
    int g = (int)ld_idx(batch, n, g_b64);
    atomicAdd(&g_hg[g * HH + o], g_hx[(size_t)n * HH + o]);
}

__global__ void k_head(const float* __restrict__ fc1w, const float* __restrict__ fc1b,
                       const float* __restrict__ fc2w, const float* __restrict__ fc2b,
                       float* __restrict__ out) {
    int g = threadIdx.x;
    if (g >= GG) return;
    float h[64];
#pragma unroll
    for (int i = 0; i < 64; i++) h[i] = g_hg[g * 64 + i];
    float o = fc2b[0];
    for (int j = 0; j < 32; j++) {
        float s = fc1b[j];
#pragma unroll
        for (int i = 0; i < 64; i++) s = fmaf(h[i], fc1w[i * 32 + j], s);
        o = fmaf(lrelu(s), fc2w[j], o);
    }
    out[g] = o;
}

// ---------------- launch ------------------------------------------------------
extern "C" void kernel_launch(void* const* d_in, const int* in_sizes, int n_in,
                              void* d_out, int out_size) {
    const float* x     = (const float*)d_in[0];
    const void*  eidx  = d_in[1];
    const float* ea    = (const float*)d_in[2];
    const void*  batch = d_in[3];
    const float* nfc_w = (const float*)d_in[4];
    const float* nfc_b = (const float*)d_in[5];
    const float* e1w1  = (const float*)d_in[6];
    const float* e1b1  = (const float*)d_in[7];
    const float* e1w2  = (const float*)d_in[8];
    const float* e1b2  = (const float*)d_in[9];
    const float* g1root= (const float*)d_in[10];
    const float* g1bias= (const float*)d_in[11];
    const float* e2w1  = (const float*)d_in[12];
    const float* e2b1  = (const float*)d_in[13];
    const float* e2w2  = (const float*)d_in[14];
    const float* e2b2  = (const float*)d_in[15];
    const float* g2root= (const float*)d_in[16];
    const float* g2bias= (const float*)d_in[17];
    const float* fc1w  = (const float*)d_in[18];
    const float* fc1b  = (const float*)d_in[19];
    const float* fc2w  = (const float*)d_in[20];
    const float* fc2b  = (const float*)d_in[21];
    float* out = (float*)d_out;

    k_detect<<<1, 32>>>(eidx, batch);                       // launch 1
    k_zero<<<(GN + 255) / 256, 256>>>();                    // launch 2
    k_nodefc<<<GN / 16, 256>>>(x, nfc_w, nfc_b);            // launch 3
    k_hidden<<<GE / 64, 256>>>(ea, e1w1, e1b1);             // launch 4 (ncu slot)
    k_hist<<<GE / 256, 256>>>(eidx);
    k_scan<<<1, 1024>>>();
    k_fill<<<GE / 256, 256>>>(eidx);
    k_sortnode<<<(GN + 127) / 128, 128>>>();

    dim3 gemm_grid((GN + 63) / 64, KSPLIT);

    // layer 1 (k_hidden for layer 1 already launched above)
    k_prepB<<<(KTOT * HH + 255) / 256, 256>>>(e1w2, e1b2, g1root);
    k_S<<<GN, 128>>>(eidx);
    k_gemm_ks<<<gemm_grid, 256>>>();
    k_reduce<<<(GN * HH + 255) / 256, 256>>>(g1bias);

    // layer 2
    k_prepB<<<(KTOT * HH + 255) / 256, 256>>>(e2w2, e2b2, g2root);
    k_hidden<<<GE / 64, 256>>>(ea, e2w1, e2b1);
    k_S<<<GN, 128>>>(eidx);
    k_gemm_ks<<<gemm_grid, 256>>>();
    k_reduce<<<(GN * HH + 255) / 256, 256>>>(g2bias);

    k_pool<<<GN / 4, 256>>>(batch);
    k_head<<<1, 64>>>(fc1w, fc1b, fc2w, fc2b, out);
}

// round 10
// speedup vs baseline: 1.2450x; 1.0436x over previous
#include <cuda_runtime.h>
#include <cstdint>

#define GN 10000   // nodes
#define GE 64000   // edges
#define GG 64      // graphs
#define HH 64      // hidden
#define XD 128     // input feat
#define EAD 32     // edge attr dim
#define KTOT 4224  // 4096 (S outer) + 64 (sh @ B2) + 64 (h @ root)
#define KSPLIT 11
#define KSEG (KTOT / KSPLIT)      // 384
#define BK 32
#define NCHUNK_KS (KSEG / BK)     // 12
#define EB 16      // edge batch in k_S

// ---------------- scratch (static device memory; no allocs allowed) ----------
__device__ float g_hx[GN * HH];                    // node features (in-place per layer)
__device__ float g_hidden[GE * HH];                // edge MLP hidden (relu(ea@w1+b1))
__device__ float g_S[(size_t)GN * KTOT];           // per-node bilinear accumulators + sh + h
__device__ float g_Bcat[KTOT * HH];                // [w2 as 4096x64 ; B2 ; root], row-major [k][o]
__device__ float g_part[KSPLIT][GN * HH];          // K-split partial sums
__device__ int   g_cnt[GN];
__device__ int   g_off[GN + 1];
__device__ int   g_cur[GN];
__device__ int   g_sorted[GE];
__device__ float g_hg[GG * HH];
__device__ int   g_e64;                            // edge_index is int64?
__device__ int   g_b64;                            // batch is int64?

__device__ __forceinline__ long long ld_idx(const void* p, long long i, int is64) {
    return is64 ? ((const long long*)p)[i] : (long long)((const int*)p)[i];
}
__device__ __forceinline__ float lrelu(float v) { return v >= 0.f ? v : 0.01f * v; }

// ---- packed f32x2 helpers (Blackwell FFMA2; base sm_100 PTX) -----------------
__device__ __forceinline__ uint64_t pack2(float x, float y) {
    uint64_t r;
    asm("mov.b64 %0, {%1, %2};" : "=l"(r) : "f"(x), "f"(y));
    return r;
}
__device__ __forceinline__ void unpack2(uint64_t v, float& x, float& y) {
    asm("mov.b64 {%0, %1}, %2;" : "=f"(x), "=f"(y) : "l"(v));
}
__device__ __forceinline__ void ffma2(uint64_t& acc, uint64_t a, uint64_t b) {
    asm("fma.rn.f32x2 %0, %1, %2, %0;" : "+l"(acc) : "l"(a), "l"(b));
}

// ---------------- dtype detection (parallel, one warp) -----------------------
__global__ void k_detect(const void* eidx, const void* batch) {
    int t = threadIdx.x;  // 32 threads
    const long long* p = (const long long*)eidx;
    bool ok = true;
#pragma unroll
    for (int j = 0; j < 4; j++) {
        long long v = p[t + j * 32];
        ok &= (v >= 0 && v < GN);
    }
    unsigned e_ok = __all_sync(0xFFFFFFFFu, ok);
    const long long* b = (const long long*)batch;
    bool okb = true;
#pragma unroll
    for (int j = 0; j < 2; j++) {
        long long v = b[GN / 2 - 64 + t + j * 32];
        okb &= (v >= 0 && v < GG);
    }
    unsigned b_ok = __all_sync(0xFFFFFFFFu, okb);
    if (t == 0) { g_e64 = e_ok ? 1 : 0; g_b64 = b_ok ? 1 : 0; }
}

__global__ void k_zero() {
    int i = blockIdx.x * 256 + threadIdx.x;
    if (i < GN) { g_cnt[i] = 0; g_cur[i] = 0; }
    if (i < GG * HH) g_hg[i] = 0.f;
}

// ---------------- node encoder: hx = lrelu(x @ nfc_w + nfc_b) ----------------
__global__ __launch_bounds__(256) void k_nodefc(const float* __restrict__ x,
                                                const float* __restrict__ w,
                                                const float* __restrict__ b) {
    __shared__ float ws[XD * HH];       // 32 KB
    __shared__ float xs[16][XD];        // 8 KB
    int n0 = blockIdx.x * 16;
    int t = threadIdx.x;
#pragma unroll
    for (int i = 0; i < XD * HH / 256; i++)          // 32 iters, coalesced
        ws[t + i * 256] = w[t + i * 256];
#pragma unroll
    for (int i = 0; i < 16 * XD / 256; i++) {        // 8 iters
        int idx = t + i * 256;
        xs[idx >> 7][idx & 127] = x[(size_t)(n0 + (idx >> 7)) * XD + (idx & 127)];
    }
    __syncthreads();
    int ln = t >> 4;            // 0..15 node
    int o = (t & 15) * 4;       // 4 outputs
    float4 acc = *(const float4*)&b[o];
    for (int k = 0; k < XD; k++) {
        float c = xs[ln][k];
        float4 wv = *(const float4*)&ws[k * HH + o];
        acc.x = fmaf(c, wv.x, acc.x);
        acc.y = fmaf(c, wv.y, acc.y);
        acc.z = fmaf(c, wv.z, acc.z);
        acc.w = fmaf(c, wv.w, acc.w);
    }
    float4 r = make_float4(lrelu(acc.x), lrelu(acc.y), lrelu(acc.z), lrelu(acc.w));
    *(float4*)&g_hx[(size_t)(n0 + ln) * HH + o] = r;
}

// ---------------- edge MLP hidden: relu(ea @ w1 + b1) ------------------------
// 64 edges/block, register-blocked: 4 edges x 4 outputs per thread.
__global__ __launch_bounds__(256) void k_hidden(const float* __restrict__ ea,
                                                const float* __restrict__ w1,
                                                const float* __restrict__ b1) {
    __shared__ float w1s[EAD * HH];     // 8 KB
    __shared__ float easT[EAD][68];     // transposed edge attrs, 8.5 KB
    int e0 = blockIdx.x * 64;
    int t = threadIdx.x;
#pragma unroll
    for (int i = 0; i < EAD * HH / 256; i++)         // 8 iters, coalesced
        w1s[t + i * 256] = w1[t + i * 256];
#pragma unroll
    for (int q = 0; q < 2; q++) {                    // 64 edges x 32 attrs
        int idx = t + q * 256;
        int le = idx >> 3, kq = (idx & 7) * 4;
        float4 v = *(const float4*)&ea[(size_t)(e0 + le) * EAD + kq];
        easT[kq + 0][le] = v.x;
        easT[kq + 1][le] = v.y;
        easT[kq + 2][le] = v.z;
        easT[kq + 3][le] = v.w;
    }
    __syncthreads();
    int eq = (t & 15) * 4;      // edge quad base (0..60)
    int og = (t >> 4) * 4;      // output quad base (0..60)
    float4 bv = *(const float4*)&b1[og];
    float4 acc0 = bv, acc1 = bv, acc2 = bv, acc3 = bv;
#pragma unroll
    for (int k = 0; k < EAD; k++) {
        float4 cv = *(const float4*)&easT[k][eq];
        float4 wv = *(const float4*)&w1s[k * HH + og];
        acc0.x = fmaf(cv.x, wv.x, acc0.x); acc0.y = fmaf(cv.x, wv.y, acc0.y);
        acc0.z = fmaf(cv.x, wv.z, acc0.z); acc0.w = fmaf(cv.x, wv.w, acc0.w);
        acc1.x = fmaf(cv.y, wv.x, acc1.x); acc1.y = fmaf(cv.y, wv.y, acc1.y);
        acc1.z = fmaf(cv.y, wv.z, acc1.z); acc1.w = fmaf(cv.y, wv.w, acc1.w);
        acc2.x = fmaf(cv.z, wv.x, acc2.x); acc2.y = fmaf(cv.z, wv.y, acc2.y);
        acc2.z = fmaf(cv.z, wv.z, acc2.z); acc2.w = fmaf(cv.z, wv.w, acc2.w);
        acc3.x = fmaf(cv.w, wv.x, acc3.x); acc3.y = fmaf(cv.w, wv.y, acc3.y);
        acc3.z = fmaf(cv.w, wv.z, acc3.z); acc3.w = fmaf(cv.w, wv.w, acc3.w);
    }
    float4 r;
    r = make_float4(fmaxf(acc0.x, 0.f), fmaxf(acc0.y, 0.f), fmaxf(acc0.z, 0.f), fmaxf(acc0.w, 0.f));
    *(float4*)&g_hidden[(size_t)(e0 + eq + 0) * HH + og] = r;
    r = make_float4(fmaxf(acc1.x, 0.f), fmaxf(acc1.y, 0.f), fmaxf(acc1.z, 0.f), fmaxf(acc1.w, 0.f));
    *(float4*)&g_hidden[(size_t)(e0 + eq + 1) * HH + og] = r;
    r = make_float4(fmaxf(acc2.x, 0.f), fmaxf(acc2.y, 0.f), fmaxf(acc2.z, 0.f), fmaxf(acc2.w, 0.f));
    *(float4*)&g_hidden[(size_t)(e0 + eq + 2) * HH + og] = r;
    r = make_float4(fmaxf(acc3.x, 0.f), fmaxf(acc3.y, 0.f), fmaxf(acc3.z, 0.f), fmaxf(acc3.w, 0.f));
    *(float4*)&g_hidden[(size_t)(e0 + eq + 3) * HH + og] = r;
}

// ---------------- CSR build (counting sort by dst, deterministic) ------------
__global__ void k_hist(const void* eidx) {
    int e = blockIdx.x * 256 + threadIdx.x;
    if (e >= GE) return;
    int d = (int)ld_idx(eidx, (long long)GE + e, g_e64);
    atomicAdd(&g_cnt[d], 1);
}

__global__ __launch_bounds__(1024) void k_scan() {
    __shared__ int part[1024];
    const int C = 10;
    int t = threadIdx.x;
    int base = t * C;
    int loc[C];
    int s = 0;
#pragma unroll
    for (int j = 0; j < C; j++) {
        int idx = base + j;
        int c = (idx < GN) ? g_cnt[idx] : 0;
        loc[j] = s;
        s += c;
    }
    part[t] = s;
    __syncthreads();
    for (int off = 1; off < 1024; off <<= 1) {
        int v = (t >= off) ? part[t - off] : 0;
        __syncthreads();
        part[t] += v;
        __syncthreads();
    }
    int pre = part[t] - s;  // exclusive prefix
#pragma unroll
    for (int j = 0; j < C; j++) {
        int idx = base + j;
        if (idx <= GN) g_off[idx] = pre + loc[j];
    }
}

__global__ void k_fill(const void* eidx) {
    int e = blockIdx.x * 256 + threadIdx.x;
    if (e >= GE) return;
    int d = (int)ld_idx(eidx, (long long)GE + e, g_e64);
    int pos = g_off[d] + atomicAdd(&g_cur[d], 1);
    g_sorted[pos] = e;
}

__global__ void k_sortnode() {
    int n = blockIdx.x * 128 + threadIdx.x;
    if (n >= GN) return;
    int b = g_off[n], e = g_off[n + 1];
    for (int i = b + 1; i < e; i++) {
        int v = g_sorted[i];
        int j = i - 1;
        while (j >= b && g_sorted[j] > v) { g_sorted[j + 1] = g_sorted[j]; j--; }
        g_sorted[j + 1] = v;
    }
}

// ---------------- B matrix concat: [w2(4096x64); B2(64x64); root(64x64)] -----
__global__ void k_prepB(const float* __restrict__ w2, const float* __restrict__ b2,
                        const float* __restrict__ root) {
    int idx = blockIdx.x * 256 + threadIdx.x;
    if (idx >= KTOT * HH) return;
    int r = idx >> 6, o = idx & 63;
    float v;
    if (r < 4096)       v = w2[idx];                     // (k*64+i)*64+o == k*4096+i*64+o
    else if (r < 4160)  v = b2[(r - 4096) * HH + o];
    else                v = root[(r - 4160) * HH + o];
    g_Bcat[idx] = v;
}

// ---------------- per-node S row: batched outer-product accumulation ---------
__global__ __launch_bounds__(128) void k_S(const void* eidx) {
    int n = blockIdx.x;
    int t = threadIdx.x;
    int k = t >> 1, half = t & 1;
    __shared__ float hid_s[EB][64];
    __shared__ float hsrc_s[EB][68];
    float acc[32];
#pragma unroll
    for (int q = 0; q < 32; q++) acc[q] = 0.f;
    float shacc = 0.f;
    int beg = g_off[n], end = g_off[n + 1];
    int is64 = g_e64;
    for (int b0 = beg; b0 < end; b0 += EB) {
        int nb = min(EB, end - b0);
        __syncthreads();   // previous batch's smem readers done
        for (int idx = t; idx < nb * 16; idx += 128) {
            int le = idx >> 4, q = idx & 15;
            int e = g_sorted[b0 + le];
            long long s = ld_idx(eidx, e, is64);
            *(float4*)&hid_s[le][q * 4]  = *(const float4*)&g_hidden[(size_t)e * HH + q * 4];
            *(float4*)&hsrc_s[le][q * 4] = *(const float4*)&g_hx[(size_t)s * HH + q * 4];
        }
        __syncthreads();
        for (int le = 0; le < nb; le++) {
            float c = hid_s[le][k];
            const float4* hp = (const float4*)&hsrc_s[le][half * 32];
#pragma unroll
            for (int q4 = 0; q4 < 8; q4++) {
                float4 h = hp[q4];
                acc[q4 * 4 + 0] = fmaf(c, h.x, acc[q4 * 4 + 0]);
                acc[q4 * 4 + 1] = fmaf(c, h.y, acc[q4 * 4 + 1]);
                acc[q4 * 4 + 2] = fmaf(c, h.z, acc[q4 * 4 + 2]);
                acc[q4 * 4 + 3] = fmaf(c, h.w, acc[q4 * 4 + 3]);
            }
        }
        if (t < 64) {
            for (int le = 0; le < nb; le++) shacc += hsrc_s[le][t];
        }
    }
    size_t base = (size_t)n * KTOT;
#pragma unroll
    for (int q = 0; q < 32; q += 4) {
        float4 v = make_float4(acc[q], acc[q + 1], acc[q + 2], acc[q + 3]);
        *(float4*)&g_S[base + k * 64 + half * 32 + q] = v;
    }
    if (t < 64) g_S[base + 4096 + t] = shacc;
    else        g_S[base + 4160 + (t - 64)] = g_hx[(size_t)n * HH + (t - 64)];
}

// ---------------- GEMM (K-split): g_part[ks] = S[:, ks-seg] @ Bcat[ks-seg, :]
// KSPLIT=11 -> grid 1727 CTAs = 2.92 waves of 592 (4 CTAs/SM) -> 97% balance.
// Inner loop: B read directly as packed ulonglong2 (no pack MOVs for B).
__global__ __launch_bounds__(256) void k_gemm_ks() {
    __shared__ __align__(16) float As[BK][68];   // [kk][m]
    __shared__ __align__(16) float Bs[BK][64];   // [kk][o]
    int t = threadIdx.x;
    int m0 = blockIdx.x * 64;
    int kbase = blockIdx.y * KSEG;
    int tx = t & 15, ty = t >> 4;

    uint64_t accp[4][2];
#pragma unroll
    for (int i = 0; i < 4; i++) { accp[i][0] = 0ull; accp[i][1] = 0ull; }

    int ar[2], ac4[2], aok[2];
#pragma unroll
    for (int q = 0; q < 2; q++) {
        int idx = t + 256 * q;
        ar[q] = idx >> 3;
        ac4[q] = idx & 7;
        aok[q] = (m0 + ar[q]) < GN;
    }
    float4 ra[2], rb[2];

#pragma unroll
    for (int q = 0; q < 2; q++) {
        ra[q] = aok[q] ? *(const float4*)&g_S[(size_t)(m0 + ar[q]) * KTOT + kbase + ac4[q] * 4]
                       : make_float4(0.f, 0.f, 0.f, 0.f);
        int idx = t + 256 * q;
        rb[q] = *(const float4*)&g_Bcat[(kbase + (idx >> 4)) * 64 + (idx & 15) * 4];
    }

    for (int c = 0; c < NCHUNK_KS; c++) {
        __syncthreads();
#pragma unroll
        for (int q = 0; q < 2; q++) {
            int kb = ac4[q] * 4;
            As[kb + 0][ar[q]] = ra[q].x;
            As[kb + 1][ar[q]] = ra[q].y;
            As[kb + 2][ar[q]] = ra[q].z;
            As[kb + 3][ar[q]] = ra[q].w;
            int idx = t + 256 * q;
            *(float4*)&Bs[idx >> 4][(idx & 15) * 4] = rb[q];
        }
        __syncthreads();

        if (c + 1 < NCHUNK_KS) {
            int k0 = kbase + (c + 1) * BK;
#pragma unroll
            for (int q = 0; q < 2; q++) {
                ra[q] = aok[q] ? *(const float4*)&g_S[(size_t)(m0 + ar[q]) * KTOT + k0 + ac4[q] * 4]
                               : make_float4(0.f, 0.f, 0.f, 0.f);
                int idx = t + 256 * q;
                rb[q] = *(const float4*)&g_Bcat[(k0 + (idx >> 4)) * 64 + (idx & 15) * 4];
            }
        }

#pragma unroll
        for (int kk = 0; kk < BK; kk++) {
            float4 a = *(const float4*)&As[kk][ty * 4];
            ulonglong2 Bv = *(const ulonglong2*)&Bs[kk][tx * 4];  // (b0,b1),(b2,b3) pre-packed
            uint64_t a0 = pack2(a.x, a.x);
            uint64_t a1 = pack2(a.y, a.y);
            uint64_t a2 = pack2(a.z, a.z);
            uint64_t a3 = pack2(a.w, a.w);
            ffma2(accp[0][0], a0, Bv.x); ffma2(accp[0][1], a0, Bv.y);
            ffma2(accp[1][0], a1, Bv.x); ffma2(accp[1][1], a1, Bv.y);
            ffma2(accp[2][0], a2, Bv.x); ffma2(accp[2][1], a2, Bv.y);
            ffma2(accp[3][0], a3, Bv.x); ffma2(accp[3][1], a3, Bv.y);
        }
    }

    float* outp = g_part[blockIdx.y];
    int col = tx * 4;
#pragma unroll
    for (int i = 0; i < 4; i++) {
        int row = m0 + ty * 4 + i;
        if (row < GN) {
            float v0, v1, v2, v3;
            unpack2(accp[i][0], v0, v1);
            unpack2(accp[i][1], v2, v3);
            float4 o = make_float4(v0, v1, v2, v3);
            *(float4*)&outp[(size_t)row * HH + col] = o;
        }
    }
}

// ---------------- K-split reduction + bias + leaky relu -> g_hx --------------
__global__ __launch_bounds__(256) void k_reduce(const float* __restrict__ bias) {
    int idx = blockIdx.x * 256 + threadIdx.x;   // over GN*HH
    if (idx >= GN * HH) return;
    int o = idx & 63;
    float v = 0.f;
#pragma unroll
    for (int s = 0; s < KSPLIT; s++) v += g_part[s][idx];
    g_hx[idx] = lrelu(v + bias[o]);
}

// ---------------- global_add_pool + head -------------------------------------
__global__ void k_pool(const void* batch) {
    int t = threadIdx.x;
    int n = blockIdx.x * 4 + (t >> 6);
    int o = t & 63;
    int g = (int)ld_idx(batch, n, g_b64);
    atomicAdd(&g_hg[g * HH + o], g_hx[(size_t)n * HH + o]);
}

__global__ void k_head(const float* __restrict__ fc1w, const float* __restrict__ fc1b,
                       const float* __restrict__ fc2w, const float* __restrict__ fc2b,
                       float* __restrict__ out) {
    int g = threadIdx.x;
    if (g >= GG) return;
    float h[64];
#pragma unroll
    for (int i = 0; i < 64; i++) h[i] = g_hg[g * 64 + i];
    float o = fc2b[0];
    for (int j = 0; j < 32; j++) {
        float s = fc1b[j];
#pragma unroll
        for (int i = 0; i < 64; i++) s = fmaf(h[i], fc1w[i * 32 + j], s);
        o = fmaf(lrelu(s), fc2w[j], o);
    }
    out[g] = o;
}

// ---------------- launch ------------------------------------------------------
extern "C" void kernel_launch(void* const* d_in, const int* in_sizes, int n_in,
                              void* d_out, int out_size) {
    const float* x     = (const float*)d_in[0];
    const void*  eidx  = d_in[1];
    const float* ea    = (const float*)d_in[2];
    const void*  batch = d_in[3];
    const float* nfc_w = (const float*)d_in[4];
    const float* nfc_b = (const float*)d_in[5];
    const float* e1w1  = (const float*)d_in[6];
    const float* e1b1  = (const float*)d_in[7];
    const float* e1w2  = (const float*)d_in[8];
    const float* e1b2  = (const float*)d_in[9];
    const float* g1root= (const float*)d_in[10];
    const float* g1bias= (const float*)d_in[11];
    const float* e2w1  = (const float*)d_in[12];
    const float* e2b1  = (const float*)d_in[13];
    const float* e2w2  = (const float*)d_in[14];
    const float* e2b2  = (const float*)d_in[15];
    const float* g2root= (const float*)d_in[16];
    const float* g2bias= (const float*)d_in[17];
    const float* fc1w  = (const float*)d_in[18];
    const float* fc1b  = (const float*)d_in[19];
    const float* fc2w  = (const float*)d_in[20];
    const float* fc2b  = (const float*)d_in[21];
    float* out = (float*)d_out;

    k_detect<<<1, 32>>>(eidx, batch);                       // launch 1
    k_zero<<<(GN + 255) / 256, 256>>>();                    // launch 2
    k_nodefc<<<GN / 16, 256>>>(x, nfc_w, nfc_b);            // launch 3
    k_hidden<<<GE / 64, 256>>>(ea, e1w1, e1b1);             // launch 4 (ncu slot)
    k_hist<<<GE / 256, 256>>>(eidx);
    k_scan<<<1, 1024>>>();
    k_fill<<<GE / 256, 256>>>(eidx);
    k_sortnode<<<(GN + 127) / 128, 128>>>();

    dim3 gemm_grid((GN + 63) / 64, KSPLIT);

    // layer 1 (k_hidden for layer 1 already launched above)
    k_prepB<<<(KTOT * HH + 255) / 256, 256>>>(e1w2, e1b2, g1root);
    k_S<<<GN, 128>>>(eidx);
    k_gemm_ks<<<gemm_grid, 256>>>();
    k_reduce<<<(GN * HH + 255) / 256, 256>>>(g1bias);

    // layer 2
    k_prepB<<<(KTOT * HH + 255) / 256, 256>>>(e2w2, e2b2, g2root);
    k_hidden<<<GE / 64, 256>>>(ea, e2w1, e2b1);
    k_S<<<GN, 128>>>(eidx);
    k_gemm_ks<<<gemm_grid, 256>>>();
    k_reduce<<<(GN * HH + 255) / 256, 256>>>(g2bias);

    k_pool<<<GN / 4, 256>>>(batch);
    k_head<<<1, 64>>>(fc1w, fc1b, fc2w, fc2b, out);
}